// round 2
// baseline (speedup 1.0000x reference)
#include <cuda_runtime.h>

#define IMG_W 1280
#define IMG_H 1024
#define IMG_B 8
#define N_CH  3

// quads per row
#define WQ (IMG_W / 4)

__global__ __launch_bounds__(256) void synth_view_kernel(
    const float* __restrict__ img,   // [B,3,H,W]
    const float* __restrict__ disp,  // [B,1,H,W]
    const float* __restrict__ sK,    // [B,4,4]
    const float* __restrict__ tK,    // [B,4,4]
    const float* __restrict__ tv,    // [B,3]
    float* __restrict__ out)         // [B,3,H,W]
{
    const int total = IMG_B * IMG_H * WQ;
    int idx = blockIdx.x * blockDim.x + threadIdx.x;
    if (idx >= total) return;

    int b   = idx / (IMG_H * WQ);
    int rem = idx - b * (IMG_H * WQ);
    int y   = rem / WQ;
    int xq  = rem - y * WQ;
    int xbase = xq * 4;

    // ---- per-batch folded camera coefficients ----
    const float* sk = sK + b * 16;
    const float* tk = tK + b * 16;
    float fxs = __ldg(sk + 0), cxs = __ldg(sk + 2);
    float fys = __ldg(sk + 5), cys = __ldg(sk + 6);
    float fxt = __ldg(tk + 0), cxt = __ldg(tk + 2);
    float fyt = __ldg(tk + 5), cyt = __ldg(tk + 6);
    float tx = __ldg(tv + b * 3 + 0);
    float ty = __ldg(tv + b * 3 + 1);
    float tz = __ldg(tv + b * 3 + 2);

    // inv(K_src) analytic (K upper-triangular with unit bottom-right)
    float ia = 1.0f / fxs, ic = -cxs / fxs;
    float ie = 1.0f / fys, iff = -cys / fys;

    float Ax = fxt * ia,  Bx = fxt * ic + cxt,  Cx = fxt * tx + cxt * tz;
    float Ay = fyt * ie,  By = fyt * iff + cyt, Cy = fyt * ty + cyt * tz;

    const float MIN_DISP = 1.0f / 255.0f;
    const float MAX_DISP = 1.0f / 10.0f;
    const float DRANGE   = MAX_DISP - MIN_DISP;
    const float SXW = (float)IMG_W / (float)(IMG_W - 1);
    const float SYH = (float)IMG_H / (float)(IMG_H - 1);

    // ---- load 4 disparities ----
    long long drow = ((long long)b * IMG_H + y) * IMG_W + xbase;
    float4 dsp = *reinterpret_cast<const float4*>(disp + drow);
    float dv[4] = {dsp.x, dsp.y, dsp.z, dsp.w};

    float yf = (float)y;

    int   i00[4], i01[4], i10[4], i11[4];
    float wxv[4], wyv[4];

#pragma unroll
    for (int i = 0; i < 4; i++) {
        float sd    = MIN_DISP + DRANGE * dv[i];
        float depth = 1.0f / sd;
        float z     = depth + tz;
        float invz  = 1.0f / (z + 1e-7f);
        float xf    = (float)(xbase + i);
        float u = depth * (Ax * xf + Bx) + Cx;
        float v = depth * (Ay * yf + By) + Cy;
        float xs = u * invz * SXW - 0.5f;
        float ys = v * invz * SYH - 0.5f;

        float x0f = floorf(xs), y0f = floorf(ys);
        wxv[i] = xs - x0f;   // weights from UNclamped floor (border padding)
        wyv[i] = ys - y0f;

        int x0 = (int)fminf(fmaxf(x0f,        0.0f), (float)(IMG_W - 1));
        int x1 = (int)fminf(fmaxf(x0f + 1.0f, 0.0f), (float)(IMG_W - 1));
        int y0 = (int)fminf(fmaxf(y0f,        0.0f), (float)(IMG_H - 1));
        int y1 = (int)fminf(fmaxf(y0f + 1.0f, 0.0f), (float)(IMG_H - 1));

        i00[i] = y0 * IMG_W + x0;
        i01[i] = y0 * IMG_W + x1;
        i10[i] = y1 * IMG_W + x0;
        i11[i] = y1 * IMG_W + x1;
    }

    long long plane   = (long long)IMG_H * IMG_W;
    long long img_b   = (long long)b * N_CH * plane;
    long long out_row = img_b + (long long)y * IMG_W + xbase;

#pragma unroll
    for (int ch = 0; ch < N_CH; ch++) {
        const float* im = img + img_b + (long long)ch * plane;
        float rv[4];
#pragma unroll
        for (int i = 0; i < 4; i++) {
            float v00 = __ldg(im + i00[i]);
            float v01 = __ldg(im + i01[i]);
            float v10 = __ldg(im + i10[i]);
            float v11 = __ldg(im + i11[i]);
            float wx = wxv[i], wy = wyv[i];
            float omx = 1.0f - wx, omy = 1.0f - wy;
            rv[i] = v00 * omx * omy + v01 * wx * omy
                  + v10 * omx * wy  + v11 * wx * wy;
        }
        float4 r = make_float4(rv[0], rv[1], rv[2], rv[3]);
        *reinterpret_cast<float4*>(out + out_row + (long long)ch * plane) = r;
    }
}

extern "C" void kernel_launch(void* const* d_in, const int* in_sizes, int n_in,
                              void* d_out, int out_size) {
    const float* img  = (const float*)d_in[0];
    const float* disp = (const float*)d_in[1];
    const float* sK   = (const float*)d_in[2];
    const float* tK   = (const float*)d_in[3];
    const float* tv   = (const float*)d_in[4];
    float* out = (float*)d_out;

    int total  = IMG_B * IMG_H * WQ;          // 2,621,440 quads
    int block  = 256;
    int grid   = (total + block - 1) / block; // 10,240 blocks
    synth_view_kernel<<<grid, block>>>(img, disp, sK, tK, tv, out);
}